// round 3
// baseline (speedup 1.0000x reference)
#include <cuda_runtime.h>
#include <cstdint>

// Problem constants (fixed shapes from reference: B=4, C=32, H=512, W=512)
#define Bn 4
#define Cn 32
#define Hn 512
#define Wn 512
#define HWn (Hn * Wn)          // 262144
#define CHWn (Cn * HWn)        // 8388608
#define NTOT (Bn * CHWn)       // 33554432 elements = 128 MiB fp32

// Scratch for materialized directional cummax tensors (allowed: __device__ globals)
__device__ float g_x1[NTOT];   // prefix max along H (up_to_bottom)
__device__ float g_x2[NTOT];   // suffix max along H (bottom_to_up)
__device__ float g_x3[NTOT];   // prefix max along W (left_to_right)
__device__ float g_x4[NTOT];   // suffix max along W (right_to_left)

__device__ __forceinline__ float neg_inf() { return __int_as_float(0xff800000); }

// ---------------------------------------------------------------------------
// Kernel 1: vertical scans. One thread per (b,c,w) column: walk H down (x1)
// then up (x2). Lanes map to consecutive w -> fully coalesced loads/stores.
// ---------------------------------------------------------------------------
__global__ void __launch_bounds__(256) vscan_kernel(const float* __restrict__ x) {
    int t = blockIdx.x * 256 + threadIdx.x;      // t in [0, B*C*W) = 65536
    int w  = t & (Wn - 1);
    int bc = t >> 9;                             // b*C + c
    size_t base = (size_t)bc * HWn + w;
    const float* xp = x + base;
    float* o1 = g_x1 + base;
    float* o2 = g_x2 + base;

    float m = neg_inf();
    int idx = 0;
#pragma unroll 8
    for (int h = 0; h < Hn; ++h, idx += Wn) {
        m = fmaxf(m, __ldg(xp + idx));
        o1[idx] = m;
    }
    m = neg_inf();
    idx = (Hn - 1) * Wn;
#pragma unroll 8
    for (int h = 0; h < Hn; ++h, idx -= Wn) {
        m = fmaxf(m, __ldg(xp + idx));
        o2[idx] = m;
    }
}

// ---------------------------------------------------------------------------
// Kernel 2: horizontal scans. One thread per (b,c,h) row: walk W forward (x3)
// then backward (x4), float4-vectorized. Per-lane 2KB stride is absorbed by
// L1 (each thread consumes full 128B lines across 8 consecutive iterations).
// ---------------------------------------------------------------------------
__global__ void __launch_bounds__(256) hscan_kernel(const float* __restrict__ x) {
    int t = blockIdx.x * 256 + threadIdx.x;      // t in [0, B*C*H) = 65536
    size_t base = (size_t)t * Wn;
    const float4* xp = (const float4*)(x + base);
    float4* o3 = (float4*)(g_x3 + base);
    float4* o4 = (float4*)(g_x4 + base);

    float m = neg_inf();
#pragma unroll 4
    for (int i = 0; i < Wn / 4; ++i) {
        float4 v = __ldg(xp + i);
        float4 r;
        m = fmaxf(m, v.x); r.x = m;
        m = fmaxf(m, v.y); r.y = m;
        m = fmaxf(m, v.z); r.z = m;
        m = fmaxf(m, v.w); r.w = m;
        o3[i] = r;
    }
    m = neg_inf();
#pragma unroll 4
    for (int i = Wn / 4 - 1; i >= 0; --i) {
        float4 v = __ldg(xp + i);
        float4 r;
        m = fmaxf(m, v.w); r.w = m;
        m = fmaxf(m, v.z); r.z = m;
        m = fmaxf(m, v.y); r.y = m;
        m = fmaxf(m, v.x); r.x = m;
        o4[i] = r;
    }
}

// ---------------------------------------------------------------------------
// Kernel 3: fused channel contraction (1x1 conv over the 5C concat) + bias.
// Thread owns an adjacent w-pair of pixels; 32 packed f32x2 accumulators in
// registers; weights pre-duplicated {w,w} into SMEM so the hot loop is
// exactly LDS.64 + fma.rn.f32x2 (2 issue slots per FFMA2 = FMA-pipe-matched).
// ---------------------------------------------------------------------------
__global__ void __launch_bounds__(256, 2) contract_kernel(
    const float* __restrict__ x,
    const float* __restrict__ Wm,     // [32][160] row-major (o, g*32+c)
    const float* __restrict__ bias,   // [32]
    float* __restrict__ out)
{
    // ws[gc][o] = {w, w} packed in 64 bits.
    __shared__ unsigned long long ws[160 * 32];
    __shared__ unsigned long long bs[32];

    for (int i = threadIdx.x; i < 160 * 32; i += 256) {
        int o  = i / 160;                 // input layout: Wm[o*160 + gc]
        int gc = i - o * 160;
        unsigned int u = __float_as_uint(Wm[i]);
        ws[gc * 32 + o] = (unsigned long long)u | ((unsigned long long)u << 32);
    }
    if (threadIdx.x < 32) {
        unsigned int u = __float_as_uint(bias[threadIdx.x]);
        bs[threadIdx.x] = (unsigned long long)u | ((unsigned long long)u << 32);
    }
    __syncthreads();

    int pid = blockIdx.x * 256 + threadIdx.x;   // pair id in [0, B*H*W/2)
    int w2  = pid & (Wn / 2 - 1);
    int tmp = pid >> 8;                         // W/2 = 256
    int h   = tmp & (Hn - 1);
    int b   = tmp >> 9;
    size_t pix = (size_t)b * CHWn + (size_t)h * Wn + (w2 << 1);

    unsigned long long acc[32];
#pragma unroll
    for (int o = 0; o < 32; ++o) acc[o] = bs[o];

#pragma unroll 1
    for (int g = 0; g < 5; ++g) {
        const float* bp;
        if      (g == 0) bp = x;
        else if (g == 1) bp = g_x1;
        else if (g == 2) bp = g_x2;
        else if (g == 3) bp = g_x3;
        else             bp = g_x4;
        const unsigned long long* vp = (const unsigned long long*)(bp + pix);
        const unsigned long long* wrow = ws + g * 32 * 32;
#pragma unroll 4
        for (int c = 0; c < 32; ++c) {
            unsigned long long v = __ldg(vp + (size_t)c * (HWn / 2));
            const unsigned long long* wc = wrow + c * 32;
#pragma unroll
            for (int o = 0; o < 32; ++o) {
                asm("fma.rn.f32x2 %0, %1, %2, %0;"
                    : "+l"(acc[o]) : "l"(v), "l"(wc[o]));
            }
        }
    }

    // Store: per o, all lanes write consecutive 8B -> coalesced.
    unsigned long long* op = (unsigned long long*)(out + pix);
#pragma unroll
    for (int o = 0; o < 32; ++o) {
        op[(size_t)o * (HWn / 2)] = acc[o];
    }
}

// ---------------------------------------------------------------------------
// Launch: three kernels on the default stream (implicit ordering: scans
// complete before contraction). Graph-capturable: launches only.
// ---------------------------------------------------------------------------
extern "C" void kernel_launch(void* const* d_in, const int* in_sizes, int n_in,
                              void* d_out, int out_size) {
    const float* x    = (const float*)d_in[0];   // [4,32,512,512]
    const float* Wm   = (const float*)d_in[1];   // [32,160,1,1]
    const float* bias = (const float*)d_in[2];   // [32]
    float* out = (float*)d_out;                  // [4,32,512,512]

    vscan_kernel<<<(Bn * Cn * Wn) / 256, 256>>>(x);
    hscan_kernel<<<(Bn * Cn * Hn) / 256, 256>>>(x);
    contract_kernel<<<(Bn * Hn * Wn / 2) / 256, 256>>>(x, Wm, bias, out);
}

// round 4
// speedup vs baseline: 1.0550x; 1.0550x over previous
#include <cuda_runtime.h>
#include <cstdint>

// Fixed shapes: B=4, C=32, H=512, W=512
#define Bn 4
#define Cn 32
#define Hn 512
#define Wn 512
#define HWn (Hn * Wn)          // 262144
#define CHWn (Cn * HWn)        // 8388608
#define NTOT (Bn * CHWn)       // 33554432 floats

typedef unsigned long long ull;

// Scratch for materialized directional cummax tensors
__device__ float g_x1[NTOT];   // prefix max along H
__device__ float g_x2[NTOT];   // suffix max along H
__device__ float g_x3[NTOT];   // prefix max along W
__device__ float g_x4[NTOT];   // suffix max along W

__device__ __forceinline__ float neg_inf() { return __int_as_float(0xff800000); }

// ---------------------------------------------------------------------------
// Merged scan kernel: blocks [0,256) do vertical scans (one thread per
// (b,c,w) column), blocks [256,512) do horizontal scans (one thread per
// (b,c,h) row). Merging doubles resident CTAs vs two sequential kernels
// (occupancy was the vscan bottleneck: 21% occ, 48% DRAM).
// ---------------------------------------------------------------------------
__global__ void __launch_bounds__(256) scans_kernel(const float* __restrict__ x) {
    if (blockIdx.x < 256) {
        // ---- vertical: walk H down (x1) then up (x2), coalesced across w ----
        int t = blockIdx.x * 256 + threadIdx.x;      // [0, B*C*W)
        int w  = t & (Wn - 1);
        int bc = t >> 9;
        size_t base = (size_t)bc * HWn + w;
        const float* xp = x + base;
        float* o1 = g_x1 + base;
        float* o2 = g_x2 + base;

        float m = neg_inf();
        int idx = 0;
#pragma unroll 8
        for (int h = 0; h < Hn; ++h, idx += Wn) {
            m = fmaxf(m, __ldg(xp + idx));
            o1[idx] = m;
        }
        m = neg_inf();
        idx = (Hn - 1) * Wn;
#pragma unroll 8
        for (int h = 0; h < Hn; ++h, idx -= Wn) {
            m = fmaxf(m, __ldg(xp + idx));
            o2[idx] = m;
        }
    } else {
        // ---- horizontal: walk W fwd (x3) / bwd (x4), float4 per thread-row ----
        int t = (blockIdx.x - 256) * 256 + threadIdx.x;  // [0, B*C*H)
        size_t base = (size_t)t * Wn;
        const float4* xp = (const float4*)(x + base);
        float4* o3 = (float4*)(g_x3 + base);
        float4* o4 = (float4*)(g_x4 + base);

        float m = neg_inf();
#pragma unroll 4
        for (int i = 0; i < Wn / 4; ++i) {
            float4 v = __ldg(xp + i);
            float4 r;
            m = fmaxf(m, v.x); r.x = m;
            m = fmaxf(m, v.y); r.y = m;
            m = fmaxf(m, v.z); r.z = m;
            m = fmaxf(m, v.w); r.w = m;
            o3[i] = r;
        }
        m = neg_inf();
#pragma unroll 4
        for (int i = Wn / 4 - 1; i >= 0; --i) {
            float4 v = __ldg(xp + i);
            float4 r;
            m = fmaxf(m, v.w); r.w = m;
            m = fmaxf(m, v.z); r.z = m;
            m = fmaxf(m, v.y); r.y = m;
            m = fmaxf(m, v.x); r.x = m;
            o4[i] = r;
        }
    }
}

// ---------------------------------------------------------------------------
// Register-tiled contraction: block = one (b,h) row of 512 pixels.
//   threadIdx: og = tid>>6 selects an 8-wide output group (o = og*8..og*8+7),
//              pq = tid&63 selects a pixel quad (8 pixels = 4 f32x2 pairs).
// Per channel per group: 2x LDG.128 values + 8x LDS.64 dup-packed weights
// + 32x fma.rn.f32x2  ->  ~42 issue slots per 64 FMA-pipe cycles: FMA-bound.
// The 4 og-groups re-read the same value lines -> L1 hits, no extra DRAM.
// ---------------------------------------------------------------------------
__global__ void __launch_bounds__(256, 2) contract_kernel(
    const float* __restrict__ x,
    const float* __restrict__ Wm,     // [32][160] (o, g*32+c)
    const float* __restrict__ bias,   // [32]
    float* __restrict__ out)
{
    __shared__ ull ws[5 * 32 * 32];   // [g][c][o], each weight duplicated {w,w}
    __shared__ ull bs[32];

    for (int i = threadIdx.x; i < 5 * 32 * 32; i += 256) {
        int o  = i & 31;
        int gc = i >> 5;
        unsigned int u = __float_as_uint(Wm[o * 160 + gc]);
        ws[i] = (ull)u | ((ull)u << 32);
    }
    if (threadIdx.x < 32) {
        unsigned int u = __float_as_uint(bias[threadIdx.x]);
        bs[threadIdx.x] = (ull)u | ((ull)u << 32);
    }
    __syncthreads();

    int tid = threadIdx.x;
    int og  = tid >> 6;               // 0..3 -> o base = og*8
    int pq  = tid & 63;               // pixel quad -> w base = pq*8
    int bh  = blockIdx.x;             // [0, B*H)
    int h   = bh & (Hn - 1);
    int b   = bh >> 9;
    size_t pix = (size_t)b * CHWn + (size_t)h * Wn + (size_t)(pq << 3);

    ull acc[8][4];
#pragma unroll
    for (int o = 0; o < 8; ++o) {
        ull bv = bs[og * 8 + o];
#pragma unroll
        for (int p = 0; p < 4; ++p) acc[o][p] = bv;
    }

#pragma unroll 1
    for (int g = 0; g < 5; ++g) {
        const float* bp;
        if      (g == 0) bp = x;
        else if (g == 1) bp = g_x1;
        else if (g == 2) bp = g_x2;
        else if (g == 3) bp = g_x3;
        else             bp = g_x4;
        const ulonglong2* vp = (const ulonglong2*)(bp + pix);  // stride HWn/4 per c
        const ull* wg = ws + g * 1024 + og * 8;                // wg[c*32 + o]
#pragma unroll 4
        for (int c = 0; c < 32; ++c) {
            ulonglong2 va = __ldg(vp + (size_t)c * (HWn / 4));
            ulonglong2 vb = __ldg(vp + (size_t)c * (HWn / 4) + 1);
            ull v0 = va.x, v1 = va.y, v2 = vb.x, v3 = vb.y;
            const ull* wc = wg + c * 32;
#pragma unroll
            for (int o = 0; o < 8; ++o) {
                ull w = wc[o];
                asm("fma.rn.f32x2 %0, %1, %2, %0;" : "+l"(acc[o][0]) : "l"(v0), "l"(w));
                asm("fma.rn.f32x2 %0, %1, %2, %0;" : "+l"(acc[o][1]) : "l"(v1), "l"(w));
                asm("fma.rn.f32x2 %0, %1, %2, %0;" : "+l"(acc[o][2]) : "l"(v2), "l"(w));
                asm("fma.rn.f32x2 %0, %1, %2, %0;" : "+l"(acc[o][3]) : "l"(v3), "l"(w));
            }
        }
    }

    // Store: for each o, lanes (pq) write consecutive 32B -> fully coalesced.
#pragma unroll
    for (int o = 0; o < 8; ++o) {
        float* op = out + (size_t)b * CHWn + (size_t)(og * 8 + o) * HWn
                        + (size_t)h * Wn + (size_t)(pq << 3);
        ulonglong2* q = (ulonglong2*)op;
        ulonglong2 r0; r0.x = acc[o][0]; r0.y = acc[o][1];
        ulonglong2 r1; r1.x = acc[o][2]; r1.y = acc[o][3];
        q[0] = r0;
        q[1] = r1;
    }
}

// ---------------------------------------------------------------------------
extern "C" void kernel_launch(void* const* d_in, const int* in_sizes, int n_in,
                              void* d_out, int out_size) {
    const float* x    = (const float*)d_in[0];   // [4,32,512,512]
    const float* Wm   = (const float*)d_in[1];   // [32,160,1,1]
    const float* bias = (const float*)d_in[2];   // [32]
    float* out = (float*)d_out;                  // [4,32,512,512]

    scans_kernel<<<512, 256>>>(x);
    contract_kernel<<<Bn * Hn, 256>>>(x, Wm, bias, out);
}

// round 5
// speedup vs baseline: 1.3601x; 1.2892x over previous
#include <cuda_runtime.h>
#include <cstdint>

// Fixed shapes: B=4, C=32, H=512, W=512
#define Bn 4
#define Cn 32
#define Hn 512
#define Wn 512
#define HWn (Hn * Wn)          // 262144
#define CHWn (Cn * HWn)        // 8388608
#define NTOT (Bn * CHWn)       // 33554432 floats

typedef unsigned long long ull;

// Scratch for materialized directional cummax tensors
__device__ float g_x1[NTOT];   // prefix max along H
__device__ float g_x2[NTOT];   // suffix max along H
__device__ float g_x3[NTOT];   // prefix max along W
__device__ float g_x4[NTOT];   // suffix max along W

__device__ __forceinline__ float neg_inf() { return __int_as_float(0xff800000); }

// ---------------------------------------------------------------------------
// vscan: register-staged segmented scan along H.
// Block = 32 adjacent w-columns x 8 H-segments of one (b,c) image.
// Thread (ws = tid&31, seg = tid>>5) loads its 64-row segment ONCE into
// registers, publishes its segment max to smem, picks up prefix/suffix
// carries, then writes both x1 (prefix) and x2 (suffix) from registers.
// 524288 threads (8x round-3), reads x once: 384 MiB total traffic.
// ---------------------------------------------------------------------------
__global__ void __launch_bounds__(256) vscan_kernel(const float* __restrict__ x) {
    int tile = blockIdx.x;           // [0, B*C*16)
    int wt   = tile & 15;            // w-tile within image
    int bc   = tile >> 4;            // b*C + c
    int ws   = threadIdx.x & 31;
    int seg  = threadIdx.x >> 5;     // 0..7

    size_t base = (size_t)bc * HWn + (size_t)(wt * 32 + ws)
                + (size_t)seg * 64 * Wn;
    const float* xp = x + base;

    float v[64];
#pragma unroll
    for (int i = 0; i < 64; ++i) v[i] = __ldg(xp + (size_t)i * Wn);

    float m = v[0];
#pragma unroll
    for (int i = 1; i < 64; ++i) m = fmaxf(m, v[i]);

    __shared__ float segmax[8][32];
    segmax[seg][ws] = m;
    __syncthreads();

    float c1 = neg_inf();   // max of segments before mine (prefix carry)
    float c2 = neg_inf();   // max of segments after mine (suffix carry)
#pragma unroll
    for (int s = 0; s < 8; ++s) {
        float sm = segmax[s][ws];
        if (s < seg) c1 = fmaxf(c1, sm);
        if (s > seg) c2 = fmaxf(c2, sm);
    }

    float* o1 = g_x1 + base;
    float* o2 = g_x2 + base;

    float r = c1;
#pragma unroll
    for (int i = 0; i < 64; ++i) {
        r = fmaxf(r, v[i]);
        o1[(size_t)i * Wn] = r;
    }
    r = c2;
#pragma unroll
    for (int i = 63; i >= 0; --i) {
        r = fmaxf(r, v[i]);
        o2[(size_t)i * Wn] = r;
    }
}

// ---------------------------------------------------------------------------
// hscan: warp-per-row shfl scan along W.
// Warp owns one (b,c,h) row of 512 floats; processes 128-element float4
// chunks with a 5-step shfl inclusive cummax + cross-chunk carry.
// Forward pass (x3), then backward pass (x4) re-hits the 2 KB row in L1.
// 2M threads, fully coalesced loads/stores.
// ---------------------------------------------------------------------------
__global__ void __launch_bounds__(256) hscan_kernel(const float* __restrict__ x) {
    int gwarp = (blockIdx.x * 256 + threadIdx.x) >> 5;   // row id [0, B*C*H)
    int lane  = threadIdx.x & 31;
    size_t base = (size_t)gwarp * Wn;
    const float4* xp = (const float4*)(x + base);
    float4* o3 = (float4*)(g_x3 + base);
    float4* o4 = (float4*)(g_x4 + base);

    // ---- forward (x3) ----
    float carry = neg_inf();
#pragma unroll
    for (int ch = 0; ch < 4; ++ch) {
        float4 v = __ldg(xp + ch * 32 + lane);
        float l0 = v.x;
        float l1 = fmaxf(l0, v.y);
        float l2 = fmaxf(l1, v.z);
        float l3 = fmaxf(l2, v.w);
        float incl = l3;
#pragma unroll
        for (int d = 1; d < 32; d <<= 1) {
            float t = __shfl_up_sync(0xffffffffu, incl, d);
            if (lane >= d) incl = fmaxf(incl, t);
        }
        float excl = __shfl_up_sync(0xffffffffu, incl, 1);
        float bm = (lane == 0) ? carry : fmaxf(carry, excl);
        float4 r;
        r.x = fmaxf(bm, l0);
        r.y = fmaxf(bm, l1);
        r.z = fmaxf(bm, l2);
        r.w = fmaxf(bm, l3);
        o3[ch * 32 + lane] = r;
        carry = fmaxf(carry, __shfl_sync(0xffffffffu, incl, 31));
    }

    // ---- backward (x4) ----
    carry = neg_inf();
#pragma unroll
    for (int ch = 3; ch >= 0; --ch) {
        float4 v = __ldg(xp + ch * 32 + lane);
        float l3 = v.w;
        float l2 = fmaxf(l3, v.z);
        float l1 = fmaxf(l2, v.y);
        float l0 = fmaxf(l1, v.x);
        float incl = l0;
#pragma unroll
        for (int d = 1; d < 32; d <<= 1) {
            float t = __shfl_down_sync(0xffffffffu, incl, d);
            if (lane < 32 - d) incl = fmaxf(incl, t);
        }
        float excl = __shfl_down_sync(0xffffffffu, incl, 1);
        float bm = (lane == 31) ? carry : fmaxf(carry, excl);
        float4 r;
        r.x = fmaxf(bm, l0);
        r.y = fmaxf(bm, l1);
        r.z = fmaxf(bm, l2);
        r.w = fmaxf(bm, l3);
        o4[ch * 32 + lane] = r;
        carry = fmaxf(carry, __shfl_sync(0xffffffffu, incl, 0));
    }
}

// ---------------------------------------------------------------------------
// Register-tiled contraction: block = one (b,h) row of 512 pixels.
//   og = tid>>6 selects an 8-wide output group, pq = tid&63 a pixel octet.
// Weights dup-packed {w,w} in smem, fetched as LDS.128 (4 per channel,
// broadcast) -> per-(c,g) L1 wavefronts drop from 16 to 12 vs round 3.
// Inner loop: 2 LDG.128 + 4 LDS.128 + 32 fma.rn.f32x2.
// ---------------------------------------------------------------------------
__global__ void __launch_bounds__(256, 2) contract_kernel(
    const float* __restrict__ x,
    const float* __restrict__ Wm,     // [32][160] (o, g*32+c)
    const float* __restrict__ bias,   // [32]
    float* __restrict__ out)
{
    __shared__ ull ws[5 * 32 * 32];   // [g][c][o], each weight duplicated {w,w}
    __shared__ ull bs[32];

    for (int i = threadIdx.x; i < 5 * 32 * 32; i += 256) {
        int o  = i & 31;
        int gc = i >> 5;
        unsigned int u = __float_as_uint(Wm[o * 160 + gc]);
        ws[i] = (ull)u | ((ull)u << 32);
    }
    if (threadIdx.x < 32) {
        unsigned int u = __float_as_uint(bias[threadIdx.x]);
        bs[threadIdx.x] = (ull)u | ((ull)u << 32);
    }
    __syncthreads();

    int tid = threadIdx.x;
    int og  = tid >> 6;               // 0..3 -> o base = og*8
    int pq  = tid & 63;               // pixel octet -> w base = pq*8
    int bh  = blockIdx.x;             // [0, B*H)
    int h   = bh & (Hn - 1);
    int b   = bh >> 9;
    size_t pix = (size_t)b * CHWn + (size_t)h * Wn + (size_t)(pq << 3);

    ull acc[8][4];
#pragma unroll
    for (int o = 0; o < 8; ++o) {
        ull bv = bs[og * 8 + o];
#pragma unroll
        for (int p = 0; p < 4; ++p) acc[o][p] = bv;
    }

#pragma unroll 1
    for (int g = 0; g < 5; ++g) {
        const float* bp;
        if      (g == 0) bp = x;
        else if (g == 1) bp = g_x1;
        else if (g == 2) bp = g_x2;
        else if (g == 3) bp = g_x3;
        else             bp = g_x4;
        const ulonglong2* vp = (const ulonglong2*)(bp + pix);  // stride HWn/4 per c
        const ull* wg = ws + g * 1024 + og * 8;                // wg[c*32 + o]
#pragma unroll 4
        for (int c = 0; c < 32; ++c) {
            ulonglong2 va = __ldg(vp + (size_t)c * (HWn / 4));
            ulonglong2 vb = __ldg(vp + (size_t)c * (HWn / 4) + 1);
            ull v0 = va.x, v1 = va.y, v2 = vb.x, v3 = vb.y;
            const ulonglong2* wc2 = (const ulonglong2*)(wg + c * 32);  // 16B aligned
#pragma unroll
            for (int o2 = 0; o2 < 4; ++o2) {
                ulonglong2 wp = wc2[o2];          // LDS.128 broadcast: 2 weights
                ull wa = wp.x, wb = wp.y;
                asm("fma.rn.f32x2 %0, %1, %2, %0;" : "+l"(acc[o2*2][0])   : "l"(v0), "l"(wa));
                asm("fma.rn.f32x2 %0, %1, %2, %0;" : "+l"(acc[o2*2][1])   : "l"(v1), "l"(wa));
                asm("fma.rn.f32x2 %0, %1, %2, %0;" : "+l"(acc[o2*2][2])   : "l"(v2), "l"(wa));
                asm("fma.rn.f32x2 %0, %1, %2, %0;" : "+l"(acc[o2*2][3])   : "l"(v3), "l"(wa));
                asm("fma.rn.f32x2 %0, %1, %2, %0;" : "+l"(acc[o2*2+1][0]) : "l"(v0), "l"(wb));
                asm("fma.rn.f32x2 %0, %1, %2, %0;" : "+l"(acc[o2*2+1][1]) : "l"(v1), "l"(wb));
                asm("fma.rn.f32x2 %0, %1, %2, %0;" : "+l"(acc[o2*2+1][2]) : "l"(v2), "l"(wb));
                asm("fma.rn.f32x2 %0, %1, %2, %0;" : "+l"(acc[o2*2+1][3]) : "l"(v3), "l"(wb));
            }
        }
    }

    // Store: for each o, lanes (pq) write consecutive 32B -> fully coalesced.
#pragma unroll
    for (int o = 0; o < 8; ++o) {
        float* op = out + (size_t)b * CHWn + (size_t)(og * 8 + o) * HWn
                        + (size_t)h * Wn + (size_t)(pq << 3);
        ulonglong2* q = (ulonglong2*)op;
        ulonglong2 r0; r0.x = acc[o][0]; r0.y = acc[o][1];
        ulonglong2 r1; r1.x = acc[o][2]; r1.y = acc[o][3];
        q[0] = r0;
        q[1] = r1;
    }
}

// ---------------------------------------------------------------------------
extern "C" void kernel_launch(void* const* d_in, const int* in_sizes, int n_in,
                              void* d_out, int out_size) {
    const float* x    = (const float*)d_in[0];   // [4,32,512,512]
    const float* Wm   = (const float*)d_in[1];   // [32,160,1,1]
    const float* bias = (const float*)d_in[2];   // [32]
    float* out = (float*)d_out;                  // [4,32,512,512]

    vscan_kernel<<<Bn * Cn * (Wn / 32), 256>>>(x);                 // 2048 blocks
    hscan_kernel<<<(Bn * Cn * Hn * 32) / 256, 256>>>(x);           // 8192 blocks
    contract_kernel<<<Bn * Hn, 256>>>(x, Wm, bias, out);           // 2048 blocks
}

// round 6
// speedup vs baseline: 1.6101x; 1.1838x over previous
#include <cuda_runtime.h>
#include <cstdint>

// Fixed shapes: B=4, C=32, H=512, W=512
#define Bn 4
#define Cn 32
#define Hn 512
#define Wn 512
#define HWn (Hn * Wn)          // 262144
#define CHWn (Cn * HWn)        // 8388608
#define NTOT (Bn * CHWn)       // 33554432 floats

typedef unsigned long long ull;

// Scratch only for the column (H) scans; W-scans are fused into contraction.
__device__ float g_x1[NTOT];   // prefix max along H
__device__ float g_x2[NTOT];   // suffix max along H

__device__ __forceinline__ float neg_inf() { return __int_as_float(0xff800000); }

// ---------------------------------------------------------------------------
// vscan: register-staged segmented scan along H (unchanged; 62us @ 68% DRAM).
// Block = 32 adjacent w-columns x 8 H-segments of one (b,c) image.
// ---------------------------------------------------------------------------
__global__ void __launch_bounds__(256) vscan_kernel(const float* __restrict__ x) {
    int tile = blockIdx.x;           // [0, B*C*16)
    int wt   = tile & 15;
    int bc   = tile >> 4;
    int ws   = threadIdx.x & 31;
    int seg  = threadIdx.x >> 5;     // 0..7

    size_t base = (size_t)bc * HWn + (size_t)(wt * 32 + ws)
                + (size_t)seg * 64 * Wn;
    const float* xp = x + base;

    float v[64];
#pragma unroll
    for (int i = 0; i < 64; ++i) v[i] = __ldg(xp + (size_t)i * Wn);

    float m = v[0];
#pragma unroll
    for (int i = 1; i < 64; ++i) m = fmaxf(m, v[i]);

    __shared__ float segmax[8][32];
    segmax[seg][ws] = m;
    __syncthreads();

    float c1 = neg_inf();
    float c2 = neg_inf();
#pragma unroll
    for (int s = 0; s < 8; ++s) {
        float sm = segmax[s][ws];
        if (s < seg) c1 = fmaxf(c1, sm);
        if (s > seg) c2 = fmaxf(c2, sm);
    }

    float* o1 = g_x1 + base;
    float* o2 = g_x2 + base;

    float r = c1;
#pragma unroll
    for (int i = 0; i < 64; ++i) {
        r = fmaxf(r, v[i]);
        o1[(size_t)i * Wn] = r;
    }
    r = c2;
#pragma unroll
    for (int i = 63; i >= 0; --i) {
        r = fmaxf(r, v[i]);
        o2[(size_t)i * Wn] = r;
    }
}

// 8 packed FMAs for one weight quad (LDS.128 broadcast -> 2 dup-packed weights)
__device__ __forceinline__ void fma_group(ull acc[8][4], ull v0, ull v1, ull v2, ull v3,
                                          const ull* __restrict__ wc) {
    const ulonglong2* w2 = (const ulonglong2*)wc;
#pragma unroll
    for (int o2 = 0; o2 < 4; ++o2) {
        ulonglong2 wp = w2[o2];
        ull wa = wp.x, wb = wp.y;
        asm("fma.rn.f32x2 %0, %1, %2, %0;" : "+l"(acc[o2*2][0])   : "l"(v0), "l"(wa));
        asm("fma.rn.f32x2 %0, %1, %2, %0;" : "+l"(acc[o2*2][1])   : "l"(v1), "l"(wa));
        asm("fma.rn.f32x2 %0, %1, %2, %0;" : "+l"(acc[o2*2][2])   : "l"(v2), "l"(wa));
        asm("fma.rn.f32x2 %0, %1, %2, %0;" : "+l"(acc[o2*2][3])   : "l"(v3), "l"(wa));
        asm("fma.rn.f32x2 %0, %1, %2, %0;" : "+l"(acc[o2*2+1][0]) : "l"(v0), "l"(wb));
        asm("fma.rn.f32x2 %0, %1, %2, %0;" : "+l"(acc[o2*2+1][1]) : "l"(v1), "l"(wb));
        asm("fma.rn.f32x2 %0, %1, %2, %0;" : "+l"(acc[o2*2+1][2]) : "l"(v2), "l"(wb));
        asm("fma.rn.f32x2 %0, %1, %2, %0;" : "+l"(acc[o2*2+1][3]) : "l"(v3), "l"(wb));
    }
}

// ---------------------------------------------------------------------------
// Fused W-scan + contraction. Block = one (b,h) row (2048 blocks, 256 thr).
// Dynamic smem: dup-packed weights (40KB) + bias + stage{x,x3,x4}[8ch][512].
// Per 8-channel batch:
//   scan phase: warp wi loads channel row once (LDG), computes fwd/bwd warp
//               cummax (shfl), stages x/x3/x4 into smem.
//   FMA phase : og=tid>>6 (8-output group), pq=tid&63 (8-pixel octet);
//               x1/x2 LDGs issued first (prefetch), x/x3/x4 from smem.
// Kills the hscan kernel + 640 MiB of DRAM traffic vs round 4.
// ---------------------------------------------------------------------------
__global__ void __launch_bounds__(256, 2) contract_fused_kernel(
    const float* __restrict__ x,
    const float* __restrict__ Wm,     // [32][160] (o, g*32+c)
    const float* __restrict__ bias,   // [32]
    float* __restrict__ out)
{
    extern __shared__ ull smem_dyn[];
    ull*   ws  = smem_dyn;                    // [5][32][32] dup-packed {w,w}
    ull*   bs  = ws + 5 * 32 * 32;            // [32]
    float* xs  = (float*)(bs + 32);           // [8][512]
    float* x3s = xs + 8 * 512;                // [8][512]
    float* x4s = x3s + 8 * 512;               // [8][512]

    for (int i = threadIdx.x; i < 5 * 32 * 32; i += 256) {
        int o  = i & 31;
        int gc = i >> 5;
        unsigned int u = __float_as_uint(Wm[o * 160 + gc]);
        ws[i] = (ull)u | ((ull)u << 32);
    }
    if (threadIdx.x < 32) {
        unsigned int u = __float_as_uint(bias[threadIdx.x]);
        bs[threadIdx.x] = (ull)u | ((ull)u << 32);
    }
    __syncthreads();

    int tid  = threadIdx.x;
    int lane = tid & 31;
    int wi   = tid >> 5;              // warp id 0..7 (scan phase: channel in batch)
    int og   = tid >> 6;              // output group 0..3 (FMA phase)
    int pq   = tid & 63;              // pixel octet (FMA phase)
    int bh   = blockIdx.x;
    int h    = bh & (Hn - 1);
    int b    = bh >> 9;

    size_t rowbase = (size_t)b * CHWn + (size_t)h * Wn;   // + c*HWn per channel
    size_t pixull  = (rowbase + (size_t)(pq << 3)) >> 1;  // ull index of my octet

    ull acc[8][4];
#pragma unroll
    for (int o = 0; o < 8; ++o) {
        ull bv = bs[og * 8 + o];
#pragma unroll
        for (int p = 0; p < 4; ++p) acc[o][p] = bv;
    }

#pragma unroll 1
    for (int batch = 0; batch < 4; ++batch) {
        // ---------- scan phase: warp wi handles channel c = batch*8 + wi ----------
        {
            int c = batch * 8 + wi;
            const float4* xp = (const float4*)(x + rowbase + (size_t)c * HWn);
            float4* xsp  = (float4*)(xs  + wi * 512);
            float4* x3sp = (float4*)(x3s + wi * 512);
            float4* x4sp = (float4*)(x4s + wi * 512);

            float4 v[4];
#pragma unroll
            for (int ch = 0; ch < 4; ++ch) {
                v[ch] = __ldg(xp + ch * 32 + lane);
                xsp[ch * 32 + lane] = v[ch];
            }

            // forward (x3)
            float carry = neg_inf();
#pragma unroll
            for (int ch = 0; ch < 4; ++ch) {
                float l0 = v[ch].x;
                float l1 = fmaxf(l0, v[ch].y);
                float l2 = fmaxf(l1, v[ch].z);
                float l3 = fmaxf(l2, v[ch].w);
                float incl = l3;
#pragma unroll
                for (int d = 1; d < 32; d <<= 1) {
                    float t = __shfl_up_sync(0xffffffffu, incl, d);
                    if (lane >= d) incl = fmaxf(incl, t);
                }
                float excl = __shfl_up_sync(0xffffffffu, incl, 1);
                float bm = (lane == 0) ? carry : fmaxf(carry, excl);
                float4 r;
                r.x = fmaxf(bm, l0);
                r.y = fmaxf(bm, l1);
                r.z = fmaxf(bm, l2);
                r.w = fmaxf(bm, l3);
                x3sp[ch * 32 + lane] = r;
                carry = fmaxf(carry, __shfl_sync(0xffffffffu, incl, 31));
            }

            // backward (x4)
            carry = neg_inf();
#pragma unroll
            for (int ch = 3; ch >= 0; --ch) {
                float l3 = v[ch].w;
                float l2 = fmaxf(l3, v[ch].z);
                float l1 = fmaxf(l2, v[ch].y);
                float l0 = fmaxf(l1, v[ch].x);
                float incl = l0;
#pragma unroll
                for (int d = 1; d < 32; d <<= 1) {
                    float t = __shfl_down_sync(0xffffffffu, incl, d);
                    if (lane < 32 - d) incl = fmaxf(incl, t);
                }
                float excl = __shfl_down_sync(0xffffffffu, incl, 1);
                float bm = (lane == 31) ? carry : fmaxf(carry, excl);
                float4 r;
                r.x = fmaxf(bm, l0);
                r.y = fmaxf(bm, l1);
                r.z = fmaxf(bm, l2);
                r.w = fmaxf(bm, l3);
                x4sp[ch * 32 + lane] = r;
                carry = fmaxf(carry, __shfl_sync(0xffffffffu, incl, 0));
            }
        }
        __syncthreads();

        // ---------- FMA phase: 8 channels of this batch ----------
#pragma unroll 1
        for (int cc = 0; cc < 8; ++cc) {
            int c = batch * 8 + cc;

            // Prefetch global x1/x2 first (fly under the smem work below).
            const ulonglong2* p1 = (const ulonglong2*)((const ull*)g_x1
                                   + pixull + (size_t)c * (HWn / 2));
            const ulonglong2* p2 = (const ulonglong2*)((const ull*)g_x2
                                   + pixull + (size_t)c * (HWn / 2));
            ulonglong2 a1 = __ldg(p1);
            ulonglong2 b1 = __ldg(p1 + 1);
            ulonglong2 a2 = __ldg(p2);
            ulonglong2 b2 = __ldg(p2 + 1);

            const ull* wrow = ws + c * 32 + og * 8;   // + g*1024 per group

            // g=0: x from smem
            {
                const ulonglong2* vp = (const ulonglong2*)(xs + cc * 512 + (pq << 3));
                ulonglong2 va = vp[0], vb = vp[1];
                fma_group(acc, va.x, va.y, vb.x, vb.y, wrow + 0 * 1024);
            }
            // g=3: x3 from smem
            {
                const ulonglong2* vp = (const ulonglong2*)(x3s + cc * 512 + (pq << 3));
                ulonglong2 va = vp[0], vb = vp[1];
                fma_group(acc, va.x, va.y, vb.x, vb.y, wrow + 3 * 1024);
            }
            // g=4: x4 from smem
            {
                const ulonglong2* vp = (const ulonglong2*)(x4s + cc * 512 + (pq << 3));
                ulonglong2 va = vp[0], vb = vp[1];
                fma_group(acc, va.x, va.y, vb.x, vb.y, wrow + 4 * 1024);
            }
            // g=1,2: x1/x2 (already in flight)
            fma_group(acc, a1.x, a1.y, b1.x, b1.y, wrow + 1 * 1024);
            fma_group(acc, a2.x, a2.y, b2.x, b2.y, wrow + 2 * 1024);
        }
        __syncthreads();   // before next batch overwrites the stage
    }

    // Store: for each o, lanes (pq) write consecutive 32B -> fully coalesced.
#pragma unroll
    for (int o = 0; o < 8; ++o) {
        float* op = out + (size_t)b * CHWn + (size_t)(og * 8 + o) * HWn
                        + (size_t)h * Wn + (size_t)(pq << 3);
        ulonglong2* q = (ulonglong2*)op;
        ulonglong2 r0; r0.x = acc[o][0]; r0.y = acc[o][1];
        ulonglong2 r1; r1.x = acc[o][2]; r1.y = acc[o][3];
        q[0] = r0;
        q[1] = r1;
    }
}

// ---------------------------------------------------------------------------
extern "C" void kernel_launch(void* const* d_in, const int* in_sizes, int n_in,
                              void* d_out, int out_size) {
    const float* x    = (const float*)d_in[0];   // [4,32,512,512]
    const float* Wm   = (const float*)d_in[1];   // [32,160,1,1]
    const float* bias = (const float*)d_in[2];   // [32]
    float* out = (float*)d_out;                  // [4,32,512,512]

    constexpr int SMEM_BYTES = (5 * 32 * 32 + 32) * 8      // weights + bias (ull)
                             + 3 * 8 * 512 * 4;            // x/x3/x4 stage -> 90368
    cudaFuncSetAttribute(contract_fused_kernel,
                         cudaFuncAttributeMaxDynamicSharedMemorySize, SMEM_BYTES);

    vscan_kernel<<<Bn * Cn * (Wn / 32), 256>>>(x);                      // 2048 blocks
    contract_fused_kernel<<<Bn * Hn, 256, SMEM_BYTES>>>(x, Wm, bias, out); // 2048 blocks
}